// round 4
// baseline (speedup 1.0000x reference)
#include <cuda_runtime.h>
#include <cuda_bf16.h>
#include <cstdint>

// Problem constants (from reference)
#define B_  8
#define L_  2048
#define P_  576
#define V_  32000
#define D_  2560
#define T_  (L_ - 1 + P_)      // 2623
#define N_ROWS_ (B_ * T_)      // 20984
#define IGNORE_INDEX_ (-100)

#define GRID_ 2432             // ~16 CTAs per SM on 152-SM GB300

// Persistent-grid row splicer. Each CTA (128 threads) loops over rows with
// stride gridDim.x. Per row: 5 front-batched float4 loads + 5 streaming
// stores (640 float4 / 128 threads). Index loads (img_pos, input_ids) stay
// L1-resident across iterations; no CTA launch/drain bubbles between rows.
__global__ void __launch_bounds__(128)
splice_persistent(const float* __restrict__ embed_table,     // [V, D]
                  const float* __restrict__ image_features,  // [B, P, D]
                  const int*   __restrict__ input_ids,       // [B, L]
                  const int*   __restrict__ labels,          // [B, L]
                  const int*   __restrict__ img_pos,         // [B]
                  float* __restrict__ out)
{
    const int tid = threadIdx.x;
    float* tails = out + (long long)N_ROWS_ * D_;

    for (int row = blockIdx.x; row < N_ROWS_; row += GRID_) {
        const int b = row / T_;
        const int t = row - b * T_;

        const int pos = img_pos[b];                     // L1-hot after iter 0
        const bool is_img = (t >= pos) && (t < pos + P_);

        int tok_idx = (t < pos) ? t : (t - P_ + 1);
        tok_idx = max(0, min(tok_idx, L_ - 1));

        float4* __restrict__ dst =
            reinterpret_cast<float4*>(out + (long long)row * D_);

        if (is_img) {
            const int img_idx = max(0, min(t - pos, P_ - 1));
            const float4* __restrict__ src = reinterpret_cast<const float4*>(
                image_features + ((long long)b * P_ + img_idx) * D_);
            float4 v0 = __ldcs(src + tid);
            float4 v1 = __ldcs(src + tid + 128);
            float4 v2 = __ldcs(src + tid + 256);
            float4 v3 = __ldcs(src + tid + 384);
            float4 v4 = __ldcs(src + tid + 512);
            __stcs(dst + tid,       v0);
            __stcs(dst + tid + 128, v1);
            __stcs(dst + tid + 256, v2);
            __stcs(dst + tid + 384, v3);
            __stcs(dst + tid + 512, v4);
        } else {
            const int tok = input_ids[b * L_ + tok_idx];   // L2/L1-hot
            const float4* __restrict__ src = reinterpret_cast<const float4*>(
                embed_table + (long long)tok * D_);
            float4 v0 = __ldg(src + tid);
            float4 v1 = __ldg(src + tid + 128);
            float4 v2 = __ldg(src + tid + 256);
            float4 v3 = __ldg(src + tid + 384);
            float4 v4 = __ldg(src + tid + 512);
            __stcs(dst + tid,       v0);
            __stcs(dst + tid + 128, v1);
            __stcs(dst + tid + 256, v2);
            __stcs(dst + tid + 384, v3);
            __stcs(dst + tid + 512, v4);
        }

        if (tid == 0) {
            // new_labels
            tails[row] = is_img ? (float)IGNORE_INDEX_
                                : (float)labels[b * L_ + tok_idx];
            // attention_mask (all true)
            tails[(long long)N_ROWS_ + row] = 1.0f;
            // position_ids (iota over T)
            tails[2LL * N_ROWS_ + row] = (float)t;
        }
    }
}

extern "C" void kernel_launch(void* const* d_in, const int* in_sizes, int n_in,
                              void* d_out, int out_size)
{
    const float* embed_table    = (const float*)d_in[0];
    const float* image_features = (const float*)d_in[1];
    const int*   input_ids      = (const int*)  d_in[2];
    const int*   labels         = (const int*)  d_in[3];
    const int*   img_pos        = (const int*)  d_in[4];
    float* out = (float*)d_out;

    splice_persistent<<<GRID_, 128>>>(embed_table, image_features,
                                      input_ids, labels, img_pos, out);
}

// round 5
// speedup vs baseline: 1.0562x; 1.0562x over previous
#include <cuda_runtime.h>
#include <cuda_bf16.h>
#include <cstdint>

// Problem constants (from reference)
#define B_  8
#define L_  2048
#define P_  576
#define V_  32000
#define D_  2560
#define T_  (L_ - 1 + P_)      // 2623
#define IGNORE_INDEX_ (-100)

// float4 write-through store: bypasses L2 allocation so the 215MB output
// stream does not evict the embed-table working set (~131MB vs 126MB L2).
__device__ __forceinline__ void stwt4(float4* p, float4 v) {
    asm volatile("st.global.wt.v4.f32 [%0], {%1,%2,%3,%4};"
                 :: "l"(p), "f"(v.x), "f"(v.y), "f"(v.z), "f"(v.w)
                 : "memory");
}

// One block per output row (b, t). 128 threads, 640 float4 per row ->
// exactly 5 unconditional float4 per thread, loads front-batched.
// embed_table: cached (reused, keep in L2). image_features: __ldcs
// (read-once). output: write-through (no L2 footprint).
__global__ void __launch_bounds__(128)
splice_kernel(const float* __restrict__ embed_table,     // [V, D]
              const float* __restrict__ image_features,  // [B, P, D]
              const int*   __restrict__ input_ids,       // [B, L]
              const int*   __restrict__ labels,          // [B, L]
              const int*   __restrict__ img_pos,         // [B]
              float* __restrict__ out)
{
    const int row = blockIdx.x;           // 0 .. B*T-1
    const int b = row / T_;
    const int t = row - b * T_;

    const int pos = img_pos[b];
    const bool is_img = (t >= pos) && (t < pos + P_);

    int tok_idx = (t < pos) ? t : (t - P_ + 1);
    tok_idx = max(0, min(tok_idx, L_ - 1));

    float4* __restrict__ dst =
        reinterpret_cast<float4*>(out + (long long)row * D_);

    const int tid = threadIdx.x;

    if (is_img) {
        const int img_idx = max(0, min(t - pos, P_ - 1));
        const float4* __restrict__ src = reinterpret_cast<const float4*>(
            image_features + ((long long)b * P_ + img_idx) * D_);
        float4 v0 = __ldcs(src + tid);
        float4 v1 = __ldcs(src + tid + 128);
        float4 v2 = __ldcs(src + tid + 256);
        float4 v3 = __ldcs(src + tid + 384);
        float4 v4 = __ldcs(src + tid + 512);
        stwt4(dst + tid,       v0);
        stwt4(dst + tid + 128, v1);
        stwt4(dst + tid + 256, v2);
        stwt4(dst + tid + 384, v3);
        stwt4(dst + tid + 512, v4);
    } else {
        const int tok = input_ids[b * L_ + tok_idx];
        const float4* __restrict__ src = reinterpret_cast<const float4*>(
            embed_table + (long long)tok * D_);
        float4 v0 = __ldg(src + tid);
        float4 v1 = __ldg(src + tid + 128);
        float4 v2 = __ldg(src + tid + 256);
        float4 v3 = __ldg(src + tid + 384);
        float4 v4 = __ldg(src + tid + 512);
        stwt4(dst + tid,       v0);
        stwt4(dst + tid + 128, v1);
        stwt4(dst + tid + 256, v2);
        stwt4(dst + tid + 384, v3);
        stwt4(dst + tid + 512, v4);
    }

    if (tid == 0) {
        float* tails = out + (long long)B_ * T_ * D_;
        // new_labels
        tails[row] = is_img ? (float)IGNORE_INDEX_
                            : (float)labels[b * L_ + tok_idx];
        // attention_mask (all true)
        tails[(long long)B_ * T_ + row] = 1.0f;
        // position_ids (iota over T)
        tails[2LL * B_ * T_ + row] = (float)t;
    }
}

extern "C" void kernel_launch(void* const* d_in, const int* in_sizes, int n_in,
                              void* d_out, int out_size)
{
    const float* embed_table    = (const float*)d_in[0];
    const float* image_features = (const float*)d_in[1];
    const int*   input_ids      = (const int*)  d_in[2];
    const int*   labels         = (const int*)  d_in[3];
    const int*   img_pos        = (const int*)  d_in[4];
    float* out = (float*)d_out;

    const int n_rows = B_ * T_;   // 20984
    splice_kernel<<<n_rows, 128>>>(embed_table, image_features,
                                   input_ids, labels, img_pos, out);
}